// round 17
// baseline (speedup 1.0000x reference)
#include <cuda_runtime.h>
#include <cuda_fp16.h>

#define NN 262144
#define NE 4194304
#define NG 1024
#define CIN 16
#define H 32
#define CAP 64   // max degree capacity; Poisson(16) => P(deg>=64) ~ 1e-20

// ---------------- scratch (device globals; no allocation allowed) ----------
__device__ __align__(256) __half g_agg1[NN * CIN];  // 8 MB  (fp16)
__device__ __align__(256) __half g_h1h[NN * H];     // 16 MB (fp16 h1, sole copy)
__device__ __align__(256) __half g_agg2[NN * H];    // 16 MB (fp16)
__device__ __align__(256) __half g_th[NN * H];      // 16 MB (fp16 transformed t)
__device__ __align__(256) float g_gate[NN];         // gate score, then e
__device__ __align__(256) float g_gmax[NG];
__device__ __align__(256) int   g_cursor[NN];       // degree counter; 0 at entry
__device__ __align__(256) int   g_slot[NN * CAP];   // 67 MB bucket CSR (rows 256B-aligned)
__device__ int g_gstart[NG + 1];

// ---------------- helpers ---------------------------------------------------
__device__ __forceinline__ void atomicMaxF(float* addr, float v) {
    if (v >= 0.0f) atomicMax((int*)addr, __float_as_int(v));
    else           atomicMin((unsigned int*)addr, __float_as_uint(v));
}

__device__ __forceinline__ unsigned long long pk2(float v) {
    unsigned long long r;
    asm("mov.b64 %0, {%1, %1};" : "=l"(r) : "f"(v));
    return r;
}
__device__ __forceinline__ void fma2(unsigned long long& d, unsigned long long a,
                                     unsigned long long b) {
    asm("fma.rn.f32x2 %0, %1, %2, %0;" : "+l"(d) : "l"(a), "l"(b));
}
__device__ __forceinline__ void add2(unsigned long long& d, unsigned long long a) {
    asm("add.rn.f32x2 %0, %0, %1;" : "+l"(d) : "l"(a));
}
__device__ __forceinline__ unsigned long long packf2(float lo, float hi) {
    unsigned long long r;
    asm("mov.b64 %0, {%1, %2};" : "=l"(r) : "f"(lo), "f"(hi));
    return r;
}
__device__ __forceinline__ float2 unpackf2(unsigned long long v) {
    float2 r;
    asm("mov.b64 {%0, %1}, %2;" : "=f"(r.x), "=f"(r.y) : "l"(v));
    return r;
}

// K x 32 dense layer, packed f32x2 FMA; w,b in (16B-aligned) shared memory
template <int K>
__device__ __forceinline__ void mmp(const float* __restrict__ in,
                                    const float* __restrict__ w,
                                    const float* __restrict__ b,
                                    float* __restrict__ out, bool do_relu) {
    unsigned long long acc[16];
#pragma unroll
    for (int c = 0; c < 16; c++) acc[c] = *(const unsigned long long*)(b + 2 * c);
#pragma unroll
    for (int k = 0; k < K; k++) {
        unsigned long long vv = pk2(in[k]);
        const unsigned long long* wr = (const unsigned long long*)(w + k * H);
#pragma unroll
        for (int c = 0; c < 16; c++) fma2(acc[c], vv, wr[c]);
    }
#pragma unroll
    for (int c = 0; c < 16; c++) {
        float2 v = unpackf2(acc[c]);
        if (do_relu) { v.x = fmaxf(v.x, 0.f); v.y = fmaxf(v.y, 0.f); }
        out[2 * c] = v.x; out[2 * c + 1] = v.y;
    }
}

// ---------------- bucket-CSR build (single pass, 4 edges/thread) -------------
// cursor is zero on entry (module-load zero; gather2 re-zeroes each launch).
__global__ void k_fillg(const int* __restrict__ ei, const int* __restrict__ bv) {
    int i = blockIdx.x * blockDim.x + threadIdx.x;
    if (i < NE / 4) {
        int4 s4 = __ldg((const int4*)ei + i);
        int4 d4 = __ldg((const int4*)(ei + NE) + i);
        int p0 = atomicAdd(&g_cursor[d4.x], 1);
        int p1 = atomicAdd(&g_cursor[d4.y], 1);
        int p2 = atomicAdd(&g_cursor[d4.z], 1);
        int p3 = atomicAdd(&g_cursor[d4.w], 1);
        if (p0 < CAP) g_slot[(long)d4.x * CAP + p0] = s4.x;
        if (p1 < CAP) g_slot[(long)d4.y * CAP + p1] = s4.y;
        if (p2 < CAP) g_slot[(long)d4.z * CAP + p2] = s4.z;
        if (p3 < CAP) g_slot[(long)d4.w * CAP + p3] = s4.w;
    }
    if (i < NN) {
        int b = __ldg(&bv[i]);
        int bp = (i == 0) ? -1 : __ldg(&bv[i - 1]);
        for (int g = bp + 1; g <= b; g++) g_gstart[g] = i;
        if (i == NN - 1)
            for (int g = b + 1; g <= NG; g++) g_gstart[g] = NN;
    }
    if (i < NG) g_gmax[i] = -INFINITY;
}

// ---------------- aggregation (gather, bucket rows, 16B lane loads) ----------
// layer 1: EIGHT nodes per warp (4-lane groups); lane loads float4 (16B);
// int4 index loads; packed f32x2 accumulation; fp16 output (uint2 per lane).
__global__ void k_gather1(const float* __restrict__ x) {
    int warp = (blockIdx.x * blockDim.x + threadIdx.x) >> 5;
    int lane = threadIdx.x & 31;
    int l4 = lane & 3;
    int n = warp * 8 + (lane >> 2);
    int deg = min(g_cursor[n], CAP);
    const int* row = g_slot + (long)n * CAP;
    const float4* xr = (const float4*)x;
    unsigned long long A0 = 0ull, A1 = 0ull, B0 = 0ull, B1 = 0ull;
    union U { float4 f; unsigned long long u[2]; };
    int j = 0;
    for (; j + 4 <= deg; j += 4) {
        int4 s4 = __ldg((const int4*)(row + j));
        U v0, v1, v2, v3;
        v0.f = __ldg(&xr[(long)s4.x * 4 + l4]);
        v1.f = __ldg(&xr[(long)s4.y * 4 + l4]);
        v2.f = __ldg(&xr[(long)s4.z * 4 + l4]);
        v3.f = __ldg(&xr[(long)s4.w * 4 + l4]);
        add2(A0, v0.u[0]); add2(A1, v0.u[1]);
        add2(B0, v1.u[0]); add2(B1, v1.u[1]);
        add2(A0, v2.u[0]); add2(A1, v2.u[1]);
        add2(B0, v3.u[0]); add2(B1, v3.u[1]);
    }
    for (; j < deg; j++) {
        int s = __ldg(row + j);
        U v; v.f = __ldg(&xr[(long)s * 4 + l4]);
        add2(A0, v.u[0]); add2(A1, v.u[1]);
    }
    add2(A0, B0); add2(A1, B1);
    float2 f0 = unpackf2(A0), f1 = unpackf2(A1);
    union { half2 h[2]; uint2 u; } o;
    o.h[0] = __floats2half2_rn(f0.x, f0.y);
    o.h[1] = __floats2half2_rn(f1.x, f1.y);
    ((uint2*)g_agg1)[(long)n * 4 + l4] = o.u;   // row = 16 half = 4 x uint2
}

// layer 2: EIGHT nodes per warp (4-lane groups); lane loads uint4 = 8 fp16;
// int4 index loads; HADD2-pair rows, convert once per pair, packed f32x2 acc;
// fp16 output (uint4 per lane). Resets cursor (deg) at the end.
__global__ void k_gather2() {
    int warp = (blockIdx.x * blockDim.x + threadIdx.x) >> 5;
    int lane = threadIdx.x & 31;
    int l4 = lane & 3;
    int n = warp * 8 + (lane >> 2);
    int deg = min(g_cursor[n], CAP);
    const int* row = g_slot + (long)n * CAP;
    const uint4* hr = (const uint4*)g_h1h;
    unsigned long long A0 = 0ull, A1 = 0ull, A2 = 0ull, A3 = 0ull;
    int j = 0;
    for (; j + 4 <= deg; j += 4) {
        int4 s4 = __ldg((const int4*)(row + j));
        uint4 r0 = __ldg(&hr[(long)s4.x * 4 + l4]);
        uint4 r1 = __ldg(&hr[(long)s4.y * 4 + l4]);
        uint4 r2 = __ldg(&hr[(long)s4.z * 4 + l4]);
        uint4 r3 = __ldg(&hr[(long)s4.w * 4 + l4]);
        const half2* h0 = (const half2*)&r0;
        const half2* h1 = (const half2*)&r1;
        const half2* h2 = (const half2*)&r2;
        const half2* h3 = (const half2*)&r3;
        half2 p; float2 f;
        p = __hadd2(h0[0], h1[0]); f = __half22float2(p); add2(A0, packf2(f.x, f.y));
        p = __hadd2(h0[1], h1[1]); f = __half22float2(p); add2(A1, packf2(f.x, f.y));
        p = __hadd2(h0[2], h1[2]); f = __half22float2(p); add2(A2, packf2(f.x, f.y));
        p = __hadd2(h0[3], h1[3]); f = __half22float2(p); add2(A3, packf2(f.x, f.y));
        p = __hadd2(h2[0], h3[0]); f = __half22float2(p); add2(A0, packf2(f.x, f.y));
        p = __hadd2(h2[1], h3[1]); f = __half22float2(p); add2(A1, packf2(f.x, f.y));
        p = __hadd2(h2[2], h3[2]); f = __half22float2(p); add2(A2, packf2(f.x, f.y));
        p = __hadd2(h2[3], h3[3]); f = __half22float2(p); add2(A3, packf2(f.x, f.y));
    }
    for (; j < deg; j++) {
        int s = __ldg(row + j);
        uint4 r0 = __ldg(&hr[(long)s * 4 + l4]);
        const half2* h0 = (const half2*)&r0;
        float2 f;
        f = __half22float2(h0[0]); add2(A0, packf2(f.x, f.y));
        f = __half22float2(h0[1]); add2(A1, packf2(f.x, f.y));
        f = __half22float2(h0[2]); add2(A2, packf2(f.x, f.y));
        f = __half22float2(h0[3]); add2(A3, packf2(f.x, f.y));
    }
    float2 f0 = unpackf2(A0), f1 = unpackf2(A1), f2 = unpackf2(A2), f3 = unpackf2(A3);
    union { half2 h[4]; uint4 u; } o;
    o.h[0] = __floats2half2_rn(f0.x, f0.y);
    o.h[1] = __floats2half2_rn(f1.x, f1.y);
    o.h[2] = __floats2half2_rn(f2.x, f2.y);
    o.h[3] = __floats2half2_rn(f3.x, f3.y);
    ((uint4*)g_agg2)[(long)n * 4 + l4] = o.u;   // row = 32 half = 4 x uint4
    if (l4 == 0) g_cursor[n] = 0;   // restore invariant for next launch
}

// ---------------- node-wise dense chains -------------------------------------
// layer-1 node update: in = x(fp32) + agg1(fp16); writes fp16 h1
__global__ void k_node1(const float* __restrict__ x, const float* __restrict__ w1,
                        const float* __restrict__ b1) {
    __shared__ __align__(16) float sw[CIN * H];
    __shared__ __align__(16) float sb[H];
    for (int i = threadIdx.x; i < CIN * H; i += blockDim.x) sw[i] = w1[i];
    if (threadIdx.x < H) sb[threadIdx.x] = b1[threadIdx.x];
    __syncthreads();
    int n = blockIdx.x * blockDim.x + threadIdx.x;
    float in[CIN];
    const half2* a1 = (const half2*)(g_agg1 + (long)n * CIN);
#pragma unroll
    for (int q = 0; q < CIN / 4; q++) {
        float4 a = __ldg((const float4*)(x + (long)n * CIN + q * 4));
        float2 b0 = __half22float2(a1[q * 2]);
        float2 b1f = __half22float2(a1[q * 2 + 1]);
        in[q * 4 + 0] = a.x + b0.x; in[q * 4 + 1] = a.y + b0.y;
        in[q * 4 + 2] = a.z + b1f.x; in[q * 4 + 3] = a.w + b1f.y;
    }
    float h[H];
    mmp<CIN>(in, sw, sb, h, true);
    union { half2 h2[4]; uint4 u; } pk[4];
#pragma unroll
    for (int q = 0; q < 16; q++)
        pk[q / 4].h2[q & 3] = __floats2half2_rn(h[2 * q], h[2 * q + 1]);
    uint4* oh = (uint4*)(g_h1h + (long)n * H);
#pragma unroll
    for (int q = 0; q < 4; q++) oh[q] = pk[q].u;
}

// layer-2 node update + gate net + transform net + warp-aggregated segment max
// u = h1h + agg2 (both fp16, HADD2 then convert); stores t as fp16
__global__ void k_node2(const float* __restrict__ w2, const float* __restrict__ b2,
                        const float* __restrict__ gw1, const float* __restrict__ gb1,
                        const float* __restrict__ gw2, const float* __restrict__ gb2,
                        const float* __restrict__ gw3, const float* __restrict__ gb3,
                        const float* __restrict__ aw1, const float* __restrict__ ab1,
                        const float* __restrict__ aw2, const float* __restrict__ ab2,
                        const int* __restrict__ bv) {
    __shared__ __align__(16) float s_w2[H * H], s_gw1[H * H], s_gw2[H * H];
    __shared__ __align__(16) float s_aw1[H * H], s_aw2[H * H];
    __shared__ __align__(16) float s_b2[H], s_gb1[H], s_gb2[H], s_gw3[H];
    __shared__ __align__(16) float s_ab1[H], s_ab2[H];
    __shared__ float s_gb3;
    for (int i = threadIdx.x; i < H * H; i += blockDim.x) {
        s_w2[i] = w2[i]; s_gw1[i] = gw1[i]; s_gw2[i] = gw2[i];
        s_aw1[i] = aw1[i]; s_aw2[i] = aw2[i];
    }
    if (threadIdx.x < H) {
        s_b2[threadIdx.x] = b2[threadIdx.x];
        s_gb1[threadIdx.x] = gb1[threadIdx.x];
        s_gb2[threadIdx.x] = gb2[threadIdx.x];
        s_gw3[threadIdx.x] = gw3[threadIdx.x];
        s_ab1[threadIdx.x] = ab1[threadIdx.x];
        s_ab2[threadIdx.x] = ab2[threadIdx.x];
    }
    if (threadIdx.x == 0) s_gb3 = gb3[0];
    __syncthreads();
    int n = blockIdx.x * blockDim.x + threadIdx.x;

    float u[H];
    const uint4* hh = (const uint4*)(g_h1h + (long)n * H);
    const uint4* ag = (const uint4*)(g_agg2 + (long)n * H);
#pragma unroll
    for (int q = 0; q < 4; q++) {
        uint4 ra = hh[q];
        uint4 rb = ag[q];
        const half2* ha = (const half2*)&ra;
        const half2* hb = (const half2*)&rb;
#pragma unroll
        for (int p = 0; p < 4; p++) {
            float2 f = __half22float2(__hadd2(ha[p], hb[p]));
            u[q * 8 + p * 2] = f.x; u[q * 8 + p * 2 + 1] = f.y;
        }
    }
    float h2[H], t1[H], t2[H];
    mmp<H>(u, s_w2, s_b2, h2, true);

    // gate network
    mmp<H>(h2, s_gw1, s_gb1, t1, true);
    mmp<H>(t1, s_gw2, s_gb2, t2, true);
    float gate = s_gb3;
#pragma unroll
    for (int k = 0; k < H; k++) gate = fmaf(t2[k], s_gw3[k], gate);
    g_gate[n] = gate;

    // transform network: store t (fp16)
    mmp<H>(h2, s_aw1, s_ab1, t1, true);
    mmp<H>(t1, s_aw2, s_ab2, t2, true);
    union { half2 h2v[4]; uint4 u4; } pk[4];
#pragma unroll
    for (int q = 0; q < 16; q++)
        pk[q / 4].h2v[q & 3] = __floats2half2_rn(t2[2 * q], t2[2 * q + 1]);
    uint4* ot = (uint4*)(g_th + (long)n * H);
#pragma unroll
    for (int q = 0; q < 4; q++) ot[q] = pk[q].u4;

    // segment max (bv sorted -> most warps uniform)
    int b = __ldg(&bv[n]);
    int b0 = __shfl_sync(0xffffffffu, b, 0);
    int b31 = __shfl_sync(0xffffffffu, b, 31);
    if (b0 == b31) {
        float m = gate;
#pragma unroll
        for (int st = 16; st; st >>= 1) m = fmaxf(m, __shfl_xor_sync(0xffffffffu, m, st));
        if ((threadIdx.x & 31) == 0) atomicMaxF(&g_gmax[b], m);
    } else {
        atomicMaxF(&g_gmax[b], gate);
    }
}

// ------- fused exp + denom + pooled + critic head (block per graph) ----------
__global__ void k_pool(const float* __restrict__ fw1, const float* __restrict__ fb1,
                       const float* __restrict__ fw2, const float* __restrict__ fb2,
                       const float* __restrict__ fw3, const float* __restrict__ fb3,
                       float* __restrict__ out) {
    int g = blockIdx.x;
    int start = g_gstart[g], end = g_gstart[g + 1];
    __shared__ float s_red[8][32];
    __shared__ float s_inv;
    int lane = threadIdx.x & 31, w = threadIdx.x >> 5;
    float gm = g_gmax[g];

    float d = 0.f;
    for (int n = start + threadIdx.x; n < end; n += 256) {
        float e = __expf(g_gate[n] - gm);
        g_gate[n] = e;
        d += e;
    }
#pragma unroll
    for (int st = 16; st; st >>= 1) d += __shfl_xor_sync(0xffffffffu, d, st);
    if (lane == 0) s_red[w][0] = d;
    __syncthreads();
    if (threadIdx.x == 0) {
        float t = 0.f;
#pragma unroll
        for (int i = 0; i < 8; i++) t += s_red[i][0];
        s_inv = 1.0f / fmaxf(t, 1e-16f);
    }
    __syncthreads();

    float inv = s_inv;
    float acc = 0.f;
    for (int n = start + w; n < end; n += 8) {
        float a = g_gate[n] * inv;
        acc = fmaf(a, __half2float(g_th[(long)n * H + lane]), acc);
    }
    s_red[w][lane] = acc;
    __syncthreads();

    // warp 0: pooled row -> critic head (32->32->32->1) via shfl broadcast
    if (w == 0) {
        float p = 0.f;
#pragma unroll
        for (int i = 0; i < 8; i++) p += s_red[i][lane];   // pooled[g][lane]

        float t1 = __ldg(&fb1[lane]);
#pragma unroll
        for (int k = 0; k < H; k++) {
            float pk = __shfl_sync(0xffffffffu, p, k);
            t1 = fmaf(pk, __ldg(&fw1[k * H + lane]), t1);
        }
        t1 = fmaxf(t1, 0.f);
        float t2 = __ldg(&fb2[lane]);
#pragma unroll
        for (int k = 0; k < H; k++) {
            float tk = __shfl_sync(0xffffffffu, t1, k);
            t2 = fmaf(tk, __ldg(&fw2[k * H + lane]), t2);
        }
        t2 = fmaxf(t2, 0.f);
        float prod = t2 * __ldg(&fw3[lane]);
#pragma unroll
        for (int st = 16; st; st >>= 1) prod += __shfl_xor_sync(0xffffffffu, prod, st);
        if (lane == 0) out[g] = prod + __ldg(&fb3[0]);
    }
}

// ---------------- launch -----------------------------------------------------
extern "C" void kernel_launch(void* const* d_in, const int* in_sizes, int n_in,
                              void* d_out, int out_size) {
    const float* x   = (const float*)d_in[0];
    const float* w1  = (const float*)d_in[1];
    const float* b1  = (const float*)d_in[2];
    const float* w2  = (const float*)d_in[3];
    const float* b2  = (const float*)d_in[4];
    const float* gw1 = (const float*)d_in[5];
    const float* gb1 = (const float*)d_in[6];
    const float* gw2 = (const float*)d_in[7];
    const float* gb2 = (const float*)d_in[8];
    const float* gw3 = (const float*)d_in[9];
    const float* gb3 = (const float*)d_in[10];
    const float* aw1 = (const float*)d_in[11];
    const float* ab1 = (const float*)d_in[12];
    const float* aw2 = (const float*)d_in[13];
    const float* ab2 = (const float*)d_in[14];
    const float* fw1 = (const float*)d_in[15];
    const float* fb1 = (const float*)d_in[16];
    const float* fw2 = (const float*)d_in[17];
    const float* fb2 = (const float*)d_in[18];
    const float* fw3 = (const float*)d_in[19];
    const float* fb3 = (const float*)d_in[20];
    const int*   ei  = (const int*)d_in[21];
    const int*   bv  = (const int*)d_in[22];
    float* out = (float*)d_out;

    k_fillg<<<NE / 1024, 256>>>(ei, bv);      // 1: bucket CSR (4 edges/thread)
    k_gather1<<<NN / 64, 256>>>(x);           // 2: fp16 agg1 out
    k_node1<<<NN / 256, 256>>>(x, w1, b1);    // 3
    k_gather2<<<NN / 64, 256>>>();            // 4: fp16 agg2 out  <- profiled (control)
    k_node2<<<NN / 128, 128>>>(w2, b2, gw1, gb1, gw2, gb2, gw3, gb3,
                               aw1, ab1, aw2, ab2, bv);  // 5: fp16 t out
    k_pool<<<NG, 256>>>(fw1, fb1, fw2, fb2, fw3, fb3, out);  // 6 (+critic head)
}